// round 10
// baseline (speedup 1.0000x reference)
#include <cuda_runtime.h>
#include <math.h>

// Problem dims (V,E,H,C = 50000,300,512,3; B=64,P=128,Th=64)
#define kB   64
#define kE   300
#define kH   512
#define kH4  2048
#define kPL  128
#define kHL  64
#define kC   3
#define kV   50000

// ---------------- scratch ----------------
__device__ __align__(16) float g_GXp[(size_t)kPL*kB*kH4];   // [t][b][4H]
__device__ __align__(16) float g_GXh[(size_t)kHL*kB*kH4];   // [t][b][4H]
__device__ __align__(16) float g_outp[(size_t)kB*kPL*kH];   // [b][p][h]
__device__ __align__(16) float g_outh[(size_t)kB*kHL*kH];   // [b][t][h]
__device__ __align__(16) float g_a1  [(size_t)kB*kPL*kH];   // [b][p][h]
__device__ __align__(16) float g_qWh [(size_t)kB*kHL*kH];   // [b][t][n] = outh @ W_h^T
__device__ __align__(16) float g_hT[2][kH*kB];              // [k][b] transposed hidden
__device__ __align__(16) float g_cT[2][kH*kB];              // [k][b] transposed cell
__device__ __align__(16) float g_h [2][kB*kH];              // normal (for final_rep)
__device__ __align__(16) float g_r  [kB*kH];
__device__ __align__(16) float g_rT [kH*kB];                // [k][b]
__device__ __align__(16) float g_a2 [kB*kH];
__device__ __align__(16) float g_rt [kB*kH];
__device__ __align__(16) float g_rep[kB*kH];

__device__ __forceinline__ float fsigmoid(float x) {
    return __fdividef(1.0f, 1.0f + __expf(-x));
}
__device__ __forceinline__ float ftanh(float x) {
    return 1.0f - __fdividef(2.0f, __expf(2.0f * x) + 1.0f);
}

// ---------------- utility ----------------
__global__ void zero_init() {
    int i = blockIdx.x * blockDim.x + threadIdx.x;
    if (i < kB * kH) {
        g_hT[0][i] = 0.f; g_cT[0][i] = 0.f;
        g_r[i] = 0.f; g_rT[i] = 0.f;
    }
}
__global__ void zero_h0() {
    int i = blockIdx.x * blockDim.x + threadIdx.x;
    if (i < kB * kH) g_hT[0][i] = 0.f;
}
__global__ void zero_out_k(float* out, int n) {
    int i = blockIdx.x * blockDim.x + threadIdx.x;
    if (i < n) out[i] = 0.f;
}

// ---------------- GEMM 64x64 tile, 4x4 microtile, 256 threads -------------
// C[m][n] = bias(n) + sum_k A(m,k) * W[n][k]
// mode 0: A = emb[premise gather] (K=300) -> g_GXp
// mode 1: A = emb[hyp gather]     (K=300) -> g_GXh
// mode 2: A = g_outp              (K=512) -> g_a1
// mode 3: A = g_outh              (K=512) -> g_qWh
__global__ void __launch_bounds__(256) gemm64(
    int mode, const float* __restrict__ emb, const int* __restrict__ tok,
    const float* __restrict__ W, const float* __restrict__ bias1,
    const float* __restrict__ bias2, int N, int K, int T)
{
    float* Cout = (mode == 0) ? g_GXp : (mode == 1) ? g_GXh
                : (mode == 2) ? g_a1  : g_qWh;

    __shared__ __align__(16) float As[32][68];
    __shared__ __align__(16) float Ws[32][68];

    int tid = threadIdx.x;
    int m0 = blockIdx.y * 64, n0 = blockIdx.x * 64;
    int lr  = tid & 63;
    int lks = (tid >> 6) << 3;

    const float* arow;
    if (mode <= 1) {
        int m = m0 + lr;
        int tt = m >> 6;
        int bb = m & 63;
        int tk = tok[bb * T + tt];
        tk = (tk < 0) ? 0 : ((tk >= kV) ? (kV - 1) : tk);
        arow = emb + (size_t)tk * K;
    } else if (mode == 2) {
        arow = g_outp + (size_t)(m0 + lr) * K;
    } else {
        arow = g_outh + (size_t)(m0 + lr) * K;
    }
    const float* wrow = W + (size_t)(n0 + lr) * K;

    int tx = tid & 15, ty = tid >> 4;
    float acc[4][4] = {};

    for (int k0 = 0; k0 < K; k0 += 32) {
        __syncthreads();
#pragma unroll
        for (int kk2 = 0; kk2 < 8; kk2++) {
            int k = k0 + lks + kk2;
            As[lks + kk2][lr] = (k < K) ? arow[k] : 0.f;
            Ws[lks + kk2][lr] = (k < K) ? wrow[k] : 0.f;
        }
        __syncthreads();
#pragma unroll
        for (int kk = 0; kk < 32; kk++) {
            float4 a = *(const float4*)&As[kk][ty << 2];
            float4 w = *(const float4*)&Ws[kk][tx << 2];
            acc[0][0] += a.x * w.x; acc[0][1] += a.x * w.y;
            acc[0][2] += a.x * w.z; acc[0][3] += a.x * w.w;
            acc[1][0] += a.y * w.x; acc[1][1] += a.y * w.y;
            acc[1][2] += a.y * w.z; acc[1][3] += a.y * w.w;
            acc[2][0] += a.z * w.x; acc[2][1] += a.z * w.y;
            acc[2][2] += a.z * w.z; acc[2][3] += a.z * w.w;
            acc[3][0] += a.w * w.x; acc[3][1] += a.w * w.y;
            acc[3][2] += a.w * w.z; acc[3][3] += a.w * w.w;
        }
    }
#pragma unroll
    for (int i = 0; i < 4; i++) {
        int m = m0 + (ty << 2) + i;
        float* crow = Cout + (size_t)m * N + n0 + (tx << 2);
#pragma unroll
        for (int j = 0; j < 4; j++) {
            float v = acc[i][j];
            int n = n0 + (tx << 2) + j;
            if (bias1) v += bias1[n];
            if (bias2) v += bias2[n];
            crow[j] = v;
        }
    }
}

// ---------------- fused LSTM step (GEMM + gates in one kernel) -------------
// grid 128 blocks x 256 thr. thread: b = tid&63, q = tid>>6 (gate 0..3).
// Each thread computes 4 rows n = q*512 + j_base + {0..3} of h@Whh^T, adds GX,
// exchanges gates via smem, then thread (b,q) applies LSTM update for j = j_base+q.
// h loads: coalesced scalars from hT[k][b]. w loads: warp-broadcast LDG.128.
__global__ void __launch_bounds__(256) lstm_step2(
    int phase, int t, const float* __restrict__ Whh)
{
    const float* GX = (phase == 0) ? g_GXp + (size_t)t * kB * kH4
                                   : g_GXh + (size_t)t * kB * kH4;
    const float* hT_in = g_hT[t & 1];
    const float* cT_in = g_cT[t & 1];
    float* hT_out = g_hT[(t + 1) & 1];
    float* cT_out = g_cT[(t + 1) & 1];
    float* h_out  = g_h[(t + 1) & 1];

    int tid = threadIdx.x;
    int b = tid & 63;
    int q = tid >> 6;                 // uniform per warp (64-thread groups)
    int j_base = blockIdx.x << 2;

    const float* w0 = Whh + ((size_t)q * 512 + j_base + 0) * kH;
    const float* w1 = Whh + ((size_t)q * 512 + j_base + 1) * kH;
    const float* w2 = Whh + ((size_t)q * 512 + j_base + 2) * kH;
    const float* w3 = Whh + ((size_t)q * 512 + j_base + 3) * kH;

    float4 gx = *(const float4*)(GX + (size_t)b * kH4 + q * 512 + j_base);
    float a0 = gx.x, a1 = gx.y, a2 = gx.z, a3 = gx.w;

#pragma unroll 2
    for (int k = 0; k < kH; k += 4) {
        float h0 = hT_in[(k + 0) * 64 + b];
        float h1 = hT_in[(k + 1) * 64 + b];
        float h2 = hT_in[(k + 2) * 64 + b];
        float h3 = hT_in[(k + 3) * 64 + b];
        float4 v0 = *(const float4*)(w0 + k);
        float4 v1 = *(const float4*)(w1 + k);
        float4 v2 = *(const float4*)(w2 + k);
        float4 v3 = *(const float4*)(w3 + k);
        a0 += h0 * v0.x + h1 * v0.y + h2 * v0.z + h3 * v0.w;
        a1 += h0 * v1.x + h1 * v1.y + h2 * v1.z + h3 * v1.w;
        a2 += h0 * v2.x + h1 * v2.y + h2 * v2.z + h3 * v2.w;
        a3 += h0 * v3.x + h1 * v3.y + h2 * v3.z + h3 * v3.w;
    }

    __shared__ float sg[4][4][64];
    sg[q][0][b] = a0; sg[q][1][b] = a1; sg[q][2][b] = a2; sg[q][3][b] = a3;
    __syncthreads();

    int j = j_base + q;
    float gi = sg[0][q][b];
    float gf = sg[1][q][b];
    float gg = sg[2][q][b];
    float go = sg[3][q][b];
    float c = fsigmoid(gf) * cT_in[j * 64 + b] + fsigmoid(gi) * ftanh(gg);
    float h = fsigmoid(go) * ftanh(c);
    cT_out[j * 64 + b] = c;
    hT_out[j * 64 + b] = h;
    h_out[b * kH + j]  = h;
    if (phase == 0) g_outp[((size_t)b * kPL + t) * kH + j] = h;
    else            g_outh[((size_t)b * kHL + t) * kH + j] = h;
}

// ---------------- attention precompute (r-GEMVs only; qWh hoisted) ---------
// rows 0..511:    a2[b][n]      = qWh[b][t][n] + r.Wr[n]
// rows 512..1023: rt[b][n-512]  = tanh(r.Wt[n-512])
// grid 128 x 256. thread: b = tid&63, 2 rows = blk*8 + (tid>>6)*2.
__global__ void __launch_bounds__(256) att_pre4(
    int t, const float* __restrict__ Wr, const float* __restrict__ Wt)
{
    int tid = threadIdx.x;
    int b = tid & 63;
    int row0 = (blockIdx.x << 3) + ((tid >> 6) << 1);
    bool isA = (row0 < 512);          // uniform per block (8 | 512)

    const float* wa = isA ? (Wr + (size_t)row0 * kH)
                          : (Wt + (size_t)(row0 - 512) * kH);
    const float* wb = wa + kH;

    float a0 = 0.f, a1 = 0.f;
#pragma unroll 2
    for (int k = 0; k < kH; k += 4) {
        float r0 = g_rT[(k + 0) * 64 + b];
        float r1 = g_rT[(k + 1) * 64 + b];
        float r2 = g_rT[(k + 2) * 64 + b];
        float r3 = g_rT[(k + 3) * 64 + b];
        float4 u = *(const float4*)(wa + k);
        float4 v = *(const float4*)(wb + k);
        a0 += r0 * u.x + r1 * u.y + r2 * u.z + r3 * u.w;
        a1 += r0 * v.x + r1 * v.y + r2 * v.z + r3 * v.w;
    }
    if (isA) {
        const float* qw = g_qWh + ((size_t)b * kHL + t) * kH;
        g_a2[b * kH + row0]     = a0 + qw[row0];
        g_a2[b * kH + row0 + 1] = a1 + qw[row0 + 1];
    } else {
        g_rt[b * kH + (row0 - 512)]     = ftanh(a0);
        g_rt[b * kH + (row0 - 512) + 1] = ftanh(a1);
    }
}

// ---------------- attention scores + softmax + r update (one block per b) --
__global__ void __launch_bounds__(512) att_update(const float* __restrict__ w_att)
{
    int b = blockIdx.x;
    int tid = threadIdx.x;
    __shared__ float a2s[512];
    __shared__ float wvs[512];
    __shared__ float ss[128];
    __shared__ float red[16];

    a2s[tid] = g_a2[b * kH + tid];
    wvs[tid] = w_att[tid];
    __syncthreads();

    int p = tid >> 2, sub = tid & 3;
    const float* a1p = g_a1 + ((size_t)b * kPL + p) * kH + (sub << 7);
    const float* a2p = a2s + (sub << 7);
    const float* wvp = wvs + (sub << 7);
    float part = 0.f;
#pragma unroll 4
    for (int k = 0; k < 128; k++)
        part += wvp[k] * ftanh(a1p[k] + a2p[k]);
    part += __shfl_xor_sync(0xffffffffu, part, 1);
    part += __shfl_xor_sync(0xffffffffu, part, 2);
    if (sub == 0) ss[p] = part;
    __syncthreads();

    float v = (tid < 128) ? ss[tid] : -3.4e38f;
#pragma unroll
    for (int o = 16; o; o >>= 1) v = fmaxf(v, __shfl_xor_sync(0xffffffffu, v, o));
    if ((tid & 31) == 0) red[tid >> 5] = v;
    __syncthreads();
    float mx = red[0];
#pragma unroll
    for (int w = 1; w < 16; w++) mx = fmaxf(mx, red[w]);
    __syncthreads();

    float e = 0.f;
    if (tid < 128) e = __expf(ss[tid] - mx);
    float sv = e;
#pragma unroll
    for (int o = 16; o; o >>= 1) sv += __shfl_xor_sync(0xffffffffu, sv, o);
    if ((tid & 31) == 0) red[tid >> 5] = sv;
    __syncthreads();
    float tot = 0.f;
#pragma unroll
    for (int w = 0; w < 16; w++) tot += red[w];
    if (tid < 128) ss[tid] = __fdividef(e, tot);
    __syncthreads();

    float acc = g_rt[b * kH + tid];
    const float* op = g_outp + (size_t)b * kPL * kH + tid;
#pragma unroll 4
    for (int p2 = 0; p2 < kPL; p2++)
        acc += op[(size_t)p2 * kH] * ss[p2];
    g_r[b * kH + tid] = acc;
    g_rT[tid * 64 + b] = acc;
}

// ---------------- final: rep = tanh(r@fc1^T + b1 + hn@fc2^T + b2) ----------
__global__ void __launch_bounds__(128) final_rep(
    const float* __restrict__ w1, const float* __restrict__ b1,
    const float* __restrict__ w2, const float* __restrict__ b2)
{
    __shared__ float rs[64][33];
    __shared__ float hs[64][33];
    int tid = threadIdx.x;
    int b = tid & 63;
    int j = (blockIdx.x << 1) + (tid >> 6);
    const float* hn = g_h[0];

    float acc1 = 0.f, acc2 = 0.f;
    const float* w1p = w1 + (size_t)j * kH;
    const float* w2p = w2 + (size_t)j * kH;

    for (int k0 = 0; k0 < kH; k0 += 32) {
#pragma unroll
        for (int i = 0; i < 4; i++) {
            int l = i * 128 + tid;
            int row = l >> 3;
            int c4 = (l & 7) << 2;
            float4 rv = *(const float4*)(g_r + row * kH + k0 + c4);
            float4 hv = *(const float4*)(hn + row * kH + k0 + c4);
            rs[row][c4 + 0] = rv.x; rs[row][c4 + 1] = rv.y;
            rs[row][c4 + 2] = rv.z; rs[row][c4 + 3] = rv.w;
            hs[row][c4 + 0] = hv.x; hs[row][c4 + 1] = hv.y;
            hs[row][c4 + 2] = hv.z; hs[row][c4 + 3] = hv.w;
        }
        __syncthreads();
#pragma unroll
        for (int k = 0; k < 32; k += 4) {
            float4 w1v = *(const float4*)(w1p + k0 + k);
            float4 w2v = *(const float4*)(w2p + k0 + k);
            acc1 += rs[b][k] * w1v.x + rs[b][k + 1] * w1v.y
                  + rs[b][k + 2] * w1v.z + rs[b][k + 3] * w1v.w;
            acc2 += hs[b][k] * w2v.x + hs[b][k + 1] * w2v.y
                  + hs[b][k + 2] * w2v.z + hs[b][k + 3] * w2v.w;
        }
        __syncthreads();
    }
    g_rep[b * kH + j] = ftanh(acc1 + b1[j] + acc2 + b2[j]);
}

// ---------------- final: out = rep@fc3^T + b3 ----------
__global__ void final_out_k(const float* __restrict__ fc3w,
                            const float* __restrict__ fc3b, float* __restrict__ out)
{
    int b = blockIdx.x, c = blockIdx.y, lane = threadIdx.x;
    float acc = 0.f;
    for (int k = lane; k < kH; k += 32)
        acc += g_rep[b * kH + k] * fc3w[c * kH + k];
#pragma unroll
    for (int o = 16; o; o >>= 1) acc += __shfl_xor_sync(0xffffffffu, acc, o);
    if (lane == 0) out[b * kC + c] = acc + fc3b[c];
}

// ---------------- launch ----------------
extern "C" void kernel_launch(void* const* d_in, const int* in_sizes, int n_in,
                              void* d_out, int out_size)
{
    const void *p_tokP, *p_tokH, *p_emb, *p_fc3w, *p_fc3b;
    const void *wih[2], *whh[2], *bia[4], *sq[6], *v512[3];
    int nwih, nwhh, nbia, nsq, nv;

    auto try_bind = [&](long long mult) -> bool {
        p_tokP = p_tokH = p_emb = p_fc3w = p_fc3b = 0;
        nwih = nwhh = nbia = nsq = nv = 0;
        for (int i = 0; i < 2; i++) { wih[i] = 0; whh[i] = 0; }
        for (int i = 0; i < 4; i++) bia[i] = 0;
        for (int i = 0; i < 6; i++) sq[i] = 0;
        for (int i = 0; i < 3; i++) v512[i] = 0;
        bool over = false;
        for (int i = 0; i < n_in; i++) {
            long long s = (long long)in_sizes[i];
            const void* p = d_in[i];
            if      (s == (long long)kB * kPL * mult)  { if (p_tokP) over = true; p_tokP = p; }
            else if (s == (long long)kB * kHL * mult)  { if (p_tokH) over = true; p_tokH = p; }
            else if (s == (long long)kV * kE * mult)   { if (p_emb)  over = true; p_emb  = p; }
            else if (s == (long long)kH4 * kE * mult)  { if (nwih < 2) wih[nwih++] = p; else over = true; }
            else if (s == (long long)kH4 * kH * mult)  { if (nwhh < 2) whh[nwhh++] = p; else over = true; }
            else if (s == (long long)kH4 * mult)       { if (nbia < 4) bia[nbia++] = p; else over = true; }
            else if (s == (long long)kH * kH * mult)   { if (nsq  < 6) sq [nsq++]  = p; else over = true; }
            else if (s == (long long)kH * mult)        { if (nv   < 3) v512[nv++]  = p; else over = true; }
            else if (s == (long long)kC * kH * mult)   { if (p_fc3w) over = true; p_fc3w = p; }
            else if (s == (long long)kC * mult)        { if (p_fc3b) over = true; p_fc3b = p; }
        }
        return !over && p_tokP && p_tokH && p_emb && p_fc3w && p_fc3b &&
               nwih == 2 && nwhh == 2 && nbia == 4 && nsq == 6 && nv == 3;
    };

    bool ok = try_bind(1);
    if (!ok) ok = try_bind(4);
    if (!ok && n_in >= 22) {
        p_tokP = d_in[0];  p_tokH = d_in[1];  p_emb = d_in[2];
        wih[0] = d_in[3];  whh[0] = d_in[4];  bia[0] = d_in[5];  bia[1] = d_in[6];
        wih[1] = d_in[7];  whh[1] = d_in[8];  bia[2] = d_in[9];  bia[3] = d_in[10];
        sq[0]  = d_in[11]; sq[1]  = d_in[12]; sq[2]  = d_in[13]; sq[3] = d_in[14];
        v512[0]= d_in[15];
        sq[4]  = d_in[16]; v512[1]= d_in[17];
        sq[5]  = d_in[18]; v512[2]= d_in[19];
        p_fc3w = d_in[20]; p_fc3b = d_in[21];
        ok = true;
    }
    if (!ok) {
        int n = out_size / 4;  if (n < 1) n = 1;
        zero_out_k<<<(n + 255) / 256, 256>>>((float*)d_out, n);
        return;
    }

    const int*   premise = (const int*)p_tokP;
    const int*   hyp     = (const int*)p_tokH;
    const float* emb     = (const float*)p_emb;
    const float* Wih1 = (const float*)wih[0]; const float* Whh1 = (const float*)whh[0];
    const float* Wih2 = (const float*)wih[1]; const float* Whh2 = (const float*)whh[1];
    const float* bih1 = (const float*)bia[0]; const float* bhh1 = (const float*)bia[1];
    const float* bih2 = (const float*)bia[2]; const float* bhh2 = (const float*)bia[3];
    const float* W_y  = (const float*)sq[0];  const float* W_h  = (const float*)sq[1];
    const float* W_r  = (const float*)sq[2];  const float* W_t  = (const float*)sq[3];
    const float* fc1_w= (const float*)sq[4];  const float* fc2_w= (const float*)sq[5];
    const float* w_att= (const float*)v512[0];
    const float* fc1_b= (const float*)v512[1];const float* fc2_b= (const float*)v512[2];
    const float* fc3_w= (const float*)p_fc3w; const float* fc3_b= (const float*)p_fc3b;
    float* out = (float*)d_out;

    zero_init<<<128, 256>>>();

    // hoisted input projections (gather fused), K = E = 300
    dim3 gP(kH4 / 64, (kPL * kB) / 64);     // (32, 128)
    gemm64<<<gP, 256>>>(0, emb, premise, Wih1, bih1, bhh1, kH4, kE, kPL);
    dim3 gHyp(kH4 / 64, (kHL * kB) / 64);   // (32, 64)
    gemm64<<<gHyp, 256>>>(1, emb, hyp, Wih2, bih2, bhh2, kH4, kE, kHL);

    // premise LSTM scan (fully fused step)
    for (int t = 0; t < kPL; t++)
        lstm_step2<<<128, 256>>>(0, t, Whh1);

    // a1 = out_p @ W_y^T  (K = H = 512)
    dim3 gA1(kH / 64, (kB * kPL) / 64);     // (8, 128)
    gemm64<<<gA1, 256>>>(2, nullptr, nullptr, W_y, nullptr, nullptr, kH, kH, 0);

    // hypothesis LSTM: h0 = 0, c0 = c_p (cT ping-pong slot 0 after 128 steps)
    zero_h0<<<128, 256>>>();
    for (int t = 0; t < kHL; t++)
        lstm_step2<<<128, 256>>>(1, t, Whh2);

    // hoist q@W_h^T for all t: qWh = out_h @ W_h^T   (M=4096, N=512, K=512)
    dim3 gQ(kH / 64, (kB * kHL) / 64);      // (8, 64)
    gemm64<<<gQ, 256>>>(3, nullptr, nullptr, W_h, nullptr, nullptr, kH, kH, 0);

    // word-by-word attention scan
    for (int t = 0; t < kHL; t++) {
        att_pre4<<<128, 256>>>(t, W_r, W_t);
        att_update<<<kB, 512>>>(w_att);
    }

    // classifier head (hn_h in g_h[0] after 64 hyp steps)
    final_rep<<<256, 128>>>(fc1_w, fc1_b, fc2_w, fc2_b);
    dim3 gO(kB, kC);
    final_out_k<<<gO, 32>>>(fc3_w, fc3_b, out);
}

// round 11
// speedup vs baseline: 1.3982x; 1.3982x over previous
#include <cuda_runtime.h>
#include <math.h>

// Problem dims (V,E,H,C = 50000,300,512,3; B=64,P=128,Th=64)
#define kB   64
#define kE   300
#define kH   512
#define kH4  2048
#define kPL  128
#define kHL  64
#define kC   3
#define kV   50000

// ---------------- scratch ----------------
__device__ __align__(16) float g_GXp[(size_t)kPL*kB*kH4];   // [t][b][4H]
__device__ __align__(16) float g_GXh[(size_t)kHL*kB*kH4];   // [t][b][4H]
__device__ __align__(16) float g_outp[(size_t)kB*kPL*kH];   // [b][p][h]
__device__ __align__(16) float g_outh[(size_t)kB*kHL*kH];   // [b][t][h]
__device__ __align__(16) float g_a1  [(size_t)kB*kPL*kH];   // [b][p][h]
__device__ __align__(16) float g_qWh [(size_t)kB*kHL*kH];   // [b][t][n]
__device__ __align__(16) float g_hT[2][kH*kB];              // [k][b]
__device__ __align__(16) float g_cT[2][kH*kB];              // [k][b]
__device__ __align__(16) float g_h [2][kB*kH];              // [b][h] (final_rep)
__device__ __align__(16) float g_r  [kB*kH];
__device__ __align__(16) float g_rT [kH*kB];                // [k][b]
__device__ __align__(16) float g_a2 [kB*kH];
__device__ __align__(16) float g_rt [kB*kH];
__device__ __align__(16) float g_rep[kB*kH];

__device__ __forceinline__ float fsigmoid(float x) {
    return __fdividef(1.0f, 1.0f + __expf(-x));
}
__device__ __forceinline__ float ftanh(float x) {
    return 1.0f - __fdividef(2.0f, __expf(2.0f * x) + 1.0f);
}

// ---------------- utility ----------------
__global__ void zero_init() {
    int i = blockIdx.x * blockDim.x + threadIdx.x;
    if (i < kB * kH) {
        g_hT[0][i] = 0.f; g_cT[0][i] = 0.f;
        g_r[i] = 0.f; g_rT[i] = 0.f;
    }
}
__global__ void zero_h0() {
    int i = blockIdx.x * blockDim.x + threadIdx.x;
    if (i < kB * kH) g_hT[0][i] = 0.f;
}
__global__ void zero_out_k(float* out, int n) {
    int i = blockIdx.x * blockDim.x + threadIdx.x;
    if (i < n) out[i] = 0.f;
}

// ---------------- GEMM 64x64 tile, 4x4 microtile, 256 threads (proven R9) --
// C[m][n] = bias(n) + sum_k A(m,k) * W[n][k]
// mode 0: A = emb[premise gather] (K=300) -> g_GXp
// mode 1: A = emb[hyp gather]     (K=300) -> g_GXh
// mode 2: A = g_outp              (K=512) -> g_a1
// mode 3: A = g_outh              (K=512) -> g_qWh
__global__ void __launch_bounds__(256) gemm64(
    int mode, const float* __restrict__ emb, const int* __restrict__ tok,
    const float* __restrict__ W, const float* __restrict__ bias1,
    const float* __restrict__ bias2, int N, int K, int T)
{
    float* Cout = (mode == 0) ? g_GXp : (mode == 1) ? g_GXh
                : (mode == 2) ? g_a1  : g_qWh;

    __shared__ __align__(16) float As[32][68];
    __shared__ __align__(16) float Ws[32][68];

    int tid = threadIdx.x;
    int m0 = blockIdx.y * 64, n0 = blockIdx.x * 64;
    int lr  = tid & 63;
    int lks = (tid >> 6) << 3;

    const float* arow;
    if (mode <= 1) {
        int m = m0 + lr;
        int tt = m >> 6;
        int bb = m & 63;
        int tk = tok[bb * T + tt];
        tk = (tk < 0) ? 0 : ((tk >= kV) ? (kV - 1) : tk);
        arow = emb + (size_t)tk * K;
    } else if (mode == 2) {
        arow = g_outp + (size_t)(m0 + lr) * K;
    } else {
        arow = g_outh + (size_t)(m0 + lr) * K;
    }
    const float* wrow = W + (size_t)(n0 + lr) * K;

    int tx = tid & 15, ty = tid >> 4;
    float acc[4][4] = {};

    for (int k0 = 0; k0 < K; k0 += 32) {
        __syncthreads();
#pragma unroll
        for (int kk2 = 0; kk2 < 8; kk2++) {
            int k = k0 + lks + kk2;
            As[lks + kk2][lr] = (k < K) ? arow[k] : 0.f;
            Ws[lks + kk2][lr] = (k < K) ? wrow[k] : 0.f;
        }
        __syncthreads();
#pragma unroll
        for (int kk = 0; kk < 32; kk++) {
            float4 a = *(const float4*)&As[kk][ty << 2];
            float4 w = *(const float4*)&Ws[kk][tx << 2];
            acc[0][0] += a.x * w.x; acc[0][1] += a.x * w.y;
            acc[0][2] += a.x * w.z; acc[0][3] += a.x * w.w;
            acc[1][0] += a.y * w.x; acc[1][1] += a.y * w.y;
            acc[1][2] += a.y * w.z; acc[1][3] += a.y * w.w;
            acc[2][0] += a.z * w.x; acc[2][1] += a.z * w.y;
            acc[2][2] += a.z * w.z; acc[2][3] += a.z * w.w;
            acc[3][0] += a.w * w.x; acc[3][1] += a.w * w.y;
            acc[3][2] += a.w * w.z; acc[3][3] += a.w * w.w;
        }
    }
#pragma unroll
    for (int i = 0; i < 4; i++) {
        int m = m0 + (ty << 2) + i;
        float* crow = Cout + (size_t)m * N + n0 + (tx << 2);
#pragma unroll
        for (int j = 0; j < 4; j++) {
            float v = acc[i][j];
            int n = n0 + (tx << 2) + j;
            if (bias1) v += bias1[n];
            if (bias2) v += bias2[n];
            crow[j] = v;
        }
    }
}

// ---------------- fused LSTM step v3 ---------------------------------------
// grid 256 blocks x 256 thr. thread: b = tid&63, g = tid>>6 (gate 0..3).
// Block handles j-pair {j0, j0+1}, j0 = blk*2. Thread (b,g) computes gate rows
// n = g*512 + j0 + {0,1}:  a = GX[b][n] + sum_k hT[k][b] * Whh[n][k].
// h loads: coalesced scalar (1 wf). w loads: warp-broadcast LDG.128 (1 wf).
// Gates exchanged via smem; threads g<2 apply the LSTM update for j0+g.
__global__ void __launch_bounds__(256) lstm_step3(
    int phase, int t, const float* __restrict__ Whh)
{
    const float* GX = (phase == 0) ? g_GXp + (size_t)t * kB * kH4
                                   : g_GXh + (size_t)t * kB * kH4;
    const float* hT_in = g_hT[t & 1];
    const float* cT_in = g_cT[t & 1];
    float* hT_out = g_hT[(t + 1) & 1];
    float* cT_out = g_cT[(t + 1) & 1];
    float* h_out  = g_h[(t + 1) & 1];

    int tid = threadIdx.x;
    int b = tid & 63;
    int g = tid >> 6;                 // gate index, uniform per 2-warp group
    int j0 = blockIdx.x << 1;

    const float* w0 = Whh + ((size_t)g * 512 + j0) * kH;
    const float* w1 = w0 + kH;

    float2 gx = *(const float2*)(GX + (size_t)b * kH4 + g * 512 + j0);
    float a0 = gx.x, a1 = gx.y;

#pragma unroll 4
    for (int k = 0; k < kH; k += 4) {
        float h0 = hT_in[(k + 0) * 64 + b];
        float h1 = hT_in[(k + 1) * 64 + b];
        float h2 = hT_in[(k + 2) * 64 + b];
        float h3 = hT_in[(k + 3) * 64 + b];
        float4 u = *(const float4*)(w0 + k);
        float4 v = *(const float4*)(w1 + k);
        a0 += h0 * u.x + h1 * u.y + h2 * u.z + h3 * u.w;
        a1 += h0 * v.x + h1 * v.y + h2 * v.z + h3 * v.w;
    }

    __shared__ float sg[4][2][64];
    sg[g][0][b] = a0;
    sg[g][1][b] = a1;
    __syncthreads();

    if (g < 2) {
        int j = j0 + g;
        float gi = sg[0][g][b];
        float gf = sg[1][g][b];
        float gg = sg[2][g][b];
        float go = sg[3][g][b];
        float c = fsigmoid(gf) * cT_in[j * 64 + b] + fsigmoid(gi) * ftanh(gg);
        float h = fsigmoid(go) * ftanh(c);
        cT_out[j * 64 + b] = c;
        hT_out[j * 64 + b] = h;
        h_out[b * kH + j]  = h;
        if (phase == 0) g_outp[((size_t)b * kPL + t) * kH + j] = h;
        else            g_outh[((size_t)b * kHL + t) * kH + j] = h;
    }
}

// ---------------- attention precompute v5 (r-GEMVs; qWh hoisted) -----------
// rows 0..511:    a2[b][n]     = qWh[b][t][n] + r.Wr[n]
// rows 512..1023: rt[b][n-512] = tanh(r.Wt[n-512])
// grid 256 x 128 thr. thread: b = tid&63, pair g = tid>>6 (0..1).
// Block rows = blk*4 + g*2 + {0,1}.
__global__ void __launch_bounds__(128) att_pre5(
    int t, const float* __restrict__ Wr, const float* __restrict__ Wt)
{
    int tid = threadIdx.x;
    int b = tid & 63;
    int row0 = (blockIdx.x << 2) + ((tid >> 6) << 1);
    bool isA = (row0 < 512);          // uniform per block (4 | 512)

    const float* wa = isA ? (Wr + (size_t)row0 * kH)
                          : (Wt + (size_t)(row0 - 512) * kH);
    const float* wb = wa + kH;

    float a0 = 0.f, a1 = 0.f;
#pragma unroll 4
    for (int k = 0; k < kH; k += 4) {
        float r0 = g_rT[(k + 0) * 64 + b];
        float r1 = g_rT[(k + 1) * 64 + b];
        float r2 = g_rT[(k + 2) * 64 + b];
        float r3 = g_rT[(k + 3) * 64 + b];
        float4 u = *(const float4*)(wa + k);
        float4 v = *(const float4*)(wb + k);
        a0 += r0 * u.x + r1 * u.y + r2 * u.z + r3 * u.w;
        a1 += r0 * v.x + r1 * v.y + r2 * v.z + r3 * v.w;
    }
    if (isA) {
        const float* qw = g_qWh + ((size_t)b * kHL + t) * kH;
        g_a2[b * kH + row0]     = a0 + qw[row0];
        g_a2[b * kH + row0 + 1] = a1 + qw[row0 + 1];
    } else {
        g_rt[b * kH + (row0 - 512)]     = ftanh(a0);
        g_rt[b * kH + (row0 - 512) + 1] = ftanh(a1);
    }
}

// ---------------- attention scores + softmax + r update (one block per b) --
__global__ void __launch_bounds__(512) att_update(const float* __restrict__ w_att)
{
    int b = blockIdx.x;
    int tid = threadIdx.x;
    __shared__ float a2s[512];
    __shared__ float wvs[512];
    __shared__ float ss[128];
    __shared__ float red[16];

    a2s[tid] = g_a2[b * kH + tid];
    wvs[tid] = w_att[tid];
    __syncthreads();

    int p = tid >> 2, sub = tid & 3;
    const float* a1p = g_a1 + ((size_t)b * kPL + p) * kH + (sub << 7);
    const float* a2p = a2s + (sub << 7);
    const float* wvp = wvs + (sub << 7);
    float part = 0.f;
#pragma unroll 4
    for (int k = 0; k < 128; k++)
        part += wvp[k] * ftanh(a1p[k] + a2p[k]);
    part += __shfl_xor_sync(0xffffffffu, part, 1);
    part += __shfl_xor_sync(0xffffffffu, part, 2);
    if (sub == 0) ss[p] = part;
    __syncthreads();

    float v = (tid < 128) ? ss[tid] : -3.4e38f;
#pragma unroll
    for (int o = 16; o; o >>= 1) v = fmaxf(v, __shfl_xor_sync(0xffffffffu, v, o));
    if ((tid & 31) == 0) red[tid >> 5] = v;
    __syncthreads();
    float mx = red[0];
#pragma unroll
    for (int w = 1; w < 16; w++) mx = fmaxf(mx, red[w]);
    __syncthreads();

    float e = 0.f;
    if (tid < 128) e = __expf(ss[tid] - mx);
    float sv = e;
#pragma unroll
    for (int o = 16; o; o >>= 1) sv += __shfl_xor_sync(0xffffffffu, sv, o);
    if ((tid & 31) == 0) red[tid >> 5] = sv;
    __syncthreads();
    float tot = 0.f;
#pragma unroll
    for (int w = 0; w < 16; w++) tot += red[w];
    if (tid < 128) ss[tid] = __fdividef(e, tot);
    __syncthreads();

    float acc = g_rt[b * kH + tid];
    const float* op = g_outp + (size_t)b * kPL * kH + tid;
#pragma unroll 4
    for (int p2 = 0; p2 < kPL; p2++)
        acc += op[(size_t)p2 * kH] * ss[p2];
    g_r[b * kH + tid] = acc;
    g_rT[tid * 64 + b] = acc;
}

// ---------------- final: rep = tanh(r@fc1^T + b1 + hn@fc2^T + b2) ----------
__global__ void __launch_bounds__(128) final_rep(
    const float* __restrict__ w1, const float* __restrict__ b1,
    const float* __restrict__ w2, const float* __restrict__ b2)
{
    __shared__ float rs[64][33];
    __shared__ float hs[64][33];
    int tid = threadIdx.x;
    int b = tid & 63;
    int j = (blockIdx.x << 1) + (tid >> 6);
    const float* hn = g_h[0];

    float acc1 = 0.f, acc2 = 0.f;
    const float* w1p = w1 + (size_t)j * kH;
    const float* w2p = w2 + (size_t)j * kH;

    for (int k0 = 0; k0 < kH; k0 += 32) {
#pragma unroll
        for (int i = 0; i < 4; i++) {
            int l = i * 128 + tid;
            int row = l >> 3;
            int c4 = (l & 7) << 2;
            float4 rv = *(const float4*)(g_r + row * kH + k0 + c4);
            float4 hv = *(const float4*)(hn + row * kH + k0 + c4);
            rs[row][c4 + 0] = rv.x; rs[row][c4 + 1] = rv.y;
            rs[row][c4 + 2] = rv.z; rs[row][c4 + 3] = rv.w;
            hs[row][c4 + 0] = hv.x; hs[row][c4 + 1] = hv.y;
            hs[row][c4 + 2] = hv.z; hs[row][c4 + 3] = hv.w;
        }
        __syncthreads();
#pragma unroll
        for (int k = 0; k < 32; k += 4) {
            float4 w1v = *(const float4*)(w1p + k0 + k);
            float4 w2v = *(const float4*)(w2p + k0 + k);
            acc1 += rs[b][k] * w1v.x + rs[b][k + 1] * w1v.y
                  + rs[b][k + 2] * w1v.z + rs[b][k + 3] * w1v.w;
            acc2 += hs[b][k] * w2v.x + hs[b][k + 1] * w2v.y
                  + hs[b][k + 2] * w2v.z + hs[b][k + 3] * w2v.w;
        }
        __syncthreads();
    }
    g_rep[b * kH + j] = ftanh(acc1 + b1[j] + acc2 + b2[j]);
}

// ---------------- final: out = rep@fc3^T + b3 ----------
__global__ void final_out_k(const float* __restrict__ fc3w,
                            const float* __restrict__ fc3b, float* __restrict__ out)
{
    int b = blockIdx.x, c = blockIdx.y, lane = threadIdx.x;
    float acc = 0.f;
    for (int k = lane; k < kH; k += 32)
        acc += g_rep[b * kH + k] * fc3w[c * kH + k];
#pragma unroll
    for (int o = 16; o; o >>= 1) acc += __shfl_xor_sync(0xffffffffu, acc, o);
    if (lane == 0) out[b * kC + c] = acc + fc3b[c];
}

// ---------------- launch ----------------
extern "C" void kernel_launch(void* const* d_in, const int* in_sizes, int n_in,
                              void* d_out, int out_size)
{
    const void *p_tokP, *p_tokH, *p_emb, *p_fc3w, *p_fc3b;
    const void *wih[2], *whh[2], *bia[4], *sq[6], *v512[3];
    int nwih, nwhh, nbia, nsq, nv;

    auto try_bind = [&](long long mult) -> bool {
        p_tokP = p_tokH = p_emb = p_fc3w = p_fc3b = 0;
        nwih = nwhh = nbia = nsq = nv = 0;
        for (int i = 0; i < 2; i++) { wih[i] = 0; whh[i] = 0; }
        for (int i = 0; i < 4; i++) bia[i] = 0;
        for (int i = 0; i < 6; i++) sq[i] = 0;
        for (int i = 0; i < 3; i++) v512[i] = 0;
        bool over = false;
        for (int i = 0; i < n_in; i++) {
            long long s = (long long)in_sizes[i];
            const void* p = d_in[i];
            if      (s == (long long)kB * kPL * mult)  { if (p_tokP) over = true; p_tokP = p; }
            else if (s == (long long)kB * kHL * mult)  { if (p_tokH) over = true; p_tokH = p; }
            else if (s == (long long)kV * kE * mult)   { if (p_emb)  over = true; p_emb  = p; }
            else if (s == (long long)kH4 * kE * mult)  { if (nwih < 2) wih[nwih++] = p; else over = true; }
            else if (s == (long long)kH4 * kH * mult)  { if (nwhh < 2) whh[nwhh++] = p; else over = true; }
            else if (s == (long long)kH4 * mult)       { if (nbia < 4) bia[nbia++] = p; else over = true; }
            else if (s == (long long)kH * kH * mult)   { if (nsq  < 6) sq [nsq++]  = p; else over = true; }
            else if (s == (long long)kH * mult)        { if (nv   < 3) v512[nv++]  = p; else over = true; }
            else if (s == (long long)kC * kH * mult)   { if (p_fc3w) over = true; p_fc3w = p; }
            else if (s == (long long)kC * mult)        { if (p_fc3b) over = true; p_fc3b = p; }
        }
        return !over && p_tokP && p_tokH && p_emb && p_fc3w && p_fc3b &&
               nwih == 2 && nwhh == 2 && nbia == 4 && nsq == 6 && nv == 3;
    };

    bool ok = try_bind(1);
    if (!ok) ok = try_bind(4);
    if (!ok && n_in >= 22) {
        p_tokP = d_in[0];  p_tokH = d_in[1];  p_emb = d_in[2];
        wih[0] = d_in[3];  whh[0] = d_in[4];  bia[0] = d_in[5];  bia[1] = d_in[6];
        wih[1] = d_in[7];  whh[1] = d_in[8];  bia[2] = d_in[9];  bia[3] = d_in[10];
        sq[0]  = d_in[11]; sq[1]  = d_in[12]; sq[2]  = d_in[13]; sq[3] = d_in[14];
        v512[0]= d_in[15];
        sq[4]  = d_in[16]; v512[1]= d_in[17];
        sq[5]  = d_in[18]; v512[2]= d_in[19];
        p_fc3w = d_in[20]; p_fc3b = d_in[21];
        ok = true;
    }
    if (!ok) {
        int n = out_size / 4;  if (n < 1) n = 1;
        zero_out_k<<<(n + 255) / 256, 256>>>((float*)d_out, n);
        return;
    }

    const int*   premise = (const int*)p_tokP;
    const int*   hyp     = (const int*)p_tokH;
    const float* emb     = (const float*)p_emb;
    const float* Wih1 = (const float*)wih[0]; const float* Whh1 = (const float*)whh[0];
    const float* Wih2 = (const float*)wih[1]; const float* Whh2 = (const float*)whh[1];
    const float* bih1 = (const float*)bia[0]; const float* bhh1 = (const float*)bia[1];
    const float* bih2 = (const float*)bia[2]; const float* bhh2 = (const float*)bia[3];
    const float* W_y  = (const float*)sq[0];  const float* W_h  = (const float*)sq[1];
    const float* W_r  = (const float*)sq[2];  const float* W_t  = (const float*)sq[3];
    const float* fc1_w= (const float*)sq[4];  const float* fc2_w= (const float*)sq[5];
    const float* w_att= (const float*)v512[0];
    const float* fc1_b= (const float*)v512[1];const float* fc2_b= (const float*)v512[2];
    const float* fc3_w= (const float*)p_fc3w; const float* fc3_b= (const float*)p_fc3b;
    float* out = (float*)d_out;

    zero_init<<<128, 256>>>();

    // hoisted input projections (gather fused), K = E = 300
    dim3 gP(kH4 / 64, (kPL * kB) / 64);     // (32, 128)
    gemm64<<<gP, 256>>>(0, emb, premise, Wih1, bih1, bhh1, kH4, kE, kPL);
    dim3 gHyp(kH4 / 64, (kHL * kB) / 64);   // (32, 64)
    gemm64<<<gHyp, 256>>>(1, emb, hyp, Wih2, bih2, bhh2, kH4, kE, kHL);

    // premise LSTM scan (fused step, 256 blocks)
    for (int t = 0; t < kPL; t++)
        lstm_step3<<<256, 256>>>(0, t, Whh1);

    // a1 = out_p @ W_y^T  (K = H = 512)
    dim3 gA1(kH / 64, (kB * kPL) / 64);     // (8, 128)
    gemm64<<<gA1, 256>>>(2, nullptr, nullptr, W_y, nullptr, nullptr, kH, kH, 0);

    // hypothesis LSTM: h0 = 0, c0 = c_p (cT slot 0 after 128 premise steps)
    zero_h0<<<128, 256>>>();
    for (int t = 0; t < kHL; t++)
        lstm_step3<<<256, 256>>>(1, t, Whh2);

    // hoist q@W_h^T for all t: qWh = out_h @ W_h^T   (M=4096, N=512, K=512)
    dim3 gQ(kH / 64, (kB * kHL) / 64);      // (8, 64)
    gemm64<<<gQ, 256>>>(3, nullptr, nullptr, W_h, nullptr, nullptr, kH, kH, 0);

    // word-by-word attention scan
    for (int t = 0; t < kHL; t++) {
        att_pre5<<<256, 128>>>(t, W_r, W_t);
        att_update<<<kB, 512>>>(w_att);
    }

    // classifier head (hn_h in g_h[0] after 64 hyp steps)
    final_rep<<<256, 128>>>(fc1_w, fc1_b, fc2_w, fc2_b);
    dim3 gO(kB, kC);
    final_out_k<<<gO, 32>>>(fc3_w, fc3_b, out);
}